// round 1
// baseline (speedup 1.0000x reference)
#include <cuda_runtime.h>

// Problem constants
#define Bx 2
#define Tx 2048
#define Cx 1024
#define Hx 16
#define HDx 64
#define Mx (Bx*Tx)          // 4096
#define N_QKV (3*Cx)        // 3072

// Scratch (device globals: allocation-free per harness rules)
__device__ float g_qbuf[(size_t)Bx*Hx*Tx*HDx];   // q in [B,H,T,hd], 16 MB
__device__ float g_atto[(size_t)Bx*Tx*Cx];       // attention out [B,T,C], 16 MB

// ---------------------------------------------------------------------------
// GEMM 1: qkv = x @ W_attn + b_attn ; epilogue scatters q -> g_qbuf,
// k -> d_out k region, v -> d_out v region (both already [B,H,T,hd]).
// A: [4096,1024] row-major, B: [1024,3072] row-major.
// Tile 128x128x16, 256 threads, 8x8 per thread (split 4+4 at +64).
// ---------------------------------------------------------------------------
__global__ __launch_bounds__(256) void gemm_qkv_kernel(
    const float* __restrict__ X, const float* __restrict__ W,
    const float* __restrict__ bias,
    float* __restrict__ kout, float* __restrict__ vout)
{
    const int K = Cx, N = N_QKV;
    __shared__ float As[16][128];
    __shared__ float Bs[16][128];

    int tid = threadIdx.x;
    int tx = tid & 15, ty = tid >> 4;
    int row0 = blockIdx.y * 128;
    int col0 = blockIdx.x * 128;

    float acc[8][8];
#pragma unroll
    for (int i = 0; i < 8; i++)
#pragma unroll
        for (int j = 0; j < 8; j++) acc[i][j] = 0.f;

    for (int k0 = 0; k0 < K; k0 += 16) {
#pragma unroll
        for (int i = 0; i < 2; i++) {
            int idx = i * 256 + tid;            // 0..511
            int m = idx >> 2, k4 = (idx & 3) << 2;
            float4 av = *(const float4*)&X[(size_t)(row0 + m) * K + k0 + k4];
            As[k4 + 0][m] = av.x; As[k4 + 1][m] = av.y;
            As[k4 + 2][m] = av.z; As[k4 + 3][m] = av.w;
            int kk = idx >> 5, nn = (idx & 31) << 2;
            float4 bv = *(const float4*)&W[(size_t)(k0 + kk) * N + col0 + nn];
            *(float4*)&Bs[kk][nn] = bv;
        }
        __syncthreads();
#pragma unroll
        for (int k = 0; k < 16; k++) {
            float4 a0 = *(float4*)&As[k][ty * 4];
            float4 a1 = *(float4*)&As[k][ty * 4 + 64];
            float4 b0 = *(float4*)&Bs[k][tx * 4];
            float4 b1 = *(float4*)&Bs[k][tx * 4 + 64];
            float a[8] = {a0.x, a0.y, a0.z, a0.w, a1.x, a1.y, a1.z, a1.w};
            float b[8] = {b0.x, b0.y, b0.z, b0.w, b1.x, b1.y, b1.z, b1.w};
#pragma unroll
            for (int i = 0; i < 8; i++)
#pragma unroll
                for (int j = 0; j < 8; j++) acc[i][j] += a[i] * b[j];
        }
        __syncthreads();
    }

    // Epilogue: bias + scatter
#pragma unroll
    for (int i = 0; i < 8; i++) {
        int r = row0 + ty * 4 + ((i < 4) ? i : (60 + i));
        int bb = r >> 11;            // / 2048
        int t  = r & 2047;
#pragma unroll
        for (int j = 0; j < 8; j++) {
            int c = col0 + tx * 4 + ((j < 4) ? j : (60 + j));
            float v = acc[i][j] + bias[c];
            int sec = c >> 10;       // 0:q 1:k 2:v
            int within = c & 1023;
            int h = within >> 6, d = within & 63;
            size_t idx = ((((size_t)bb * Hx + h) * Tx) + t) * HDx + d;
            if (sec == 0)       g_qbuf[idx] = v;
            else if (sec == 1)  kout[idx] = v;
            else                vout[idx] = v;
        }
    }
}

// ---------------------------------------------------------------------------
// GEMM 2: y = atto @ W_proj + b_proj.  A: [4096,1024], B: [1024,1024].
// ---------------------------------------------------------------------------
__global__ __launch_bounds__(256) void gemm_proj_kernel(
    const float* __restrict__ W, const float* __restrict__ bias,
    float* __restrict__ Y)
{
    const int K = Cx, N = Cx;
    __shared__ float As[16][128];
    __shared__ float Bs[16][128];

    int tid = threadIdx.x;
    int tx = tid & 15, ty = tid >> 4;
    int row0 = blockIdx.y * 128;
    int col0 = blockIdx.x * 128;

    float acc[8][8];
#pragma unroll
    for (int i = 0; i < 8; i++)
#pragma unroll
        for (int j = 0; j < 8; j++) acc[i][j] = 0.f;

    for (int k0 = 0; k0 < K; k0 += 16) {
#pragma unroll
        for (int i = 0; i < 2; i++) {
            int idx = i * 256 + tid;
            int m = idx >> 2, k4 = (idx & 3) << 2;
            float4 av = *(const float4*)&g_atto[(size_t)(row0 + m) * K + k0 + k4];
            As[k4 + 0][m] = av.x; As[k4 + 1][m] = av.y;
            As[k4 + 2][m] = av.z; As[k4 + 3][m] = av.w;
            int kk = idx >> 5, nn = (idx & 31) << 2;
            float4 bv = *(const float4*)&W[(size_t)(k0 + kk) * N + col0 + nn];
            *(float4*)&Bs[kk][nn] = bv;
        }
        __syncthreads();
#pragma unroll
        for (int k = 0; k < 16; k++) {
            float4 a0 = *(float4*)&As[k][ty * 4];
            float4 a1 = *(float4*)&As[k][ty * 4 + 64];
            float4 b0 = *(float4*)&Bs[k][tx * 4];
            float4 b1 = *(float4*)&Bs[k][tx * 4 + 64];
            float a[8] = {a0.x, a0.y, a0.z, a0.w, a1.x, a1.y, a1.z, a1.w};
            float b[8] = {b0.x, b0.y, b0.z, b0.w, b1.x, b1.y, b1.z, b1.w};
#pragma unroll
            for (int i = 0; i < 8; i++)
#pragma unroll
                for (int j = 0; j < 8; j++) acc[i][j] += a[i] * b[j];
        }
        __syncthreads();
    }

#pragma unroll
    for (int i = 0; i < 8; i++) {
        int r = row0 + ty * 4 + ((i < 4) ? i : (60 + i));
        float4 o0, o1;
        o0.x = acc[i][0] + bias[col0 + tx * 4 + 0];
        o0.y = acc[i][1] + bias[col0 + tx * 4 + 1];
        o0.z = acc[i][2] + bias[col0 + tx * 4 + 2];
        o0.w = acc[i][3] + bias[col0 + tx * 4 + 3];
        o1.x = acc[i][4] + bias[col0 + tx * 4 + 64];
        o1.y = acc[i][5] + bias[col0 + tx * 4 + 65];
        o1.z = acc[i][6] + bias[col0 + tx * 4 + 66];
        o1.w = acc[i][7] + bias[col0 + tx * 4 + 67];
        *(float4*)&Y[(size_t)r * N + col0 + tx * 4]      = o0;
        *(float4*)&Y[(size_t)r * N + col0 + tx * 4 + 64] = o1;
    }
}

// ---------------------------------------------------------------------------
// Flash attention, causal. Grid: (q_tile=32, bh=32). 256 threads (16x16),
// 64x64 S tile (4x4/thread), online softmax, 16-lane shfl reductions.
// smem: Qs[64][65], Ks[64][65], Ps[64][65], Vs[64][64] = 66304 B (dynamic).
// ---------------------------------------------------------------------------
#define ATTN_SMEM_BYTES ((3*64*65 + 64*64) * 4)

__global__ __launch_bounds__(256) void attn_kernel(
    const float* __restrict__ Kall, const float* __restrict__ Vall)
{
    extern __shared__ float sm[];
    float* Qs = sm;                 // 64*65
    float* Ks = Qs + 64 * 65;       // 64*65
    float* Ps = Ks + 64 * 65;       // 64*65
    float* Vs = Ps + 64 * 65;       // 64*64

    int tid = threadIdx.x;
    int tx = tid & 15, ty = tid >> 4;
    int qt = blockIdx.x, bh = blockIdx.y;

    const float* Qg = g_qbuf + ((size_t)bh * Tx + qt * 64) * HDx;

    // Load Q tile (scaled by 1/sqrt(hd))
#pragma unroll
    for (int i = 0; i < 4; i++) {
        int idx = i * 256 + tid;               // 0..1023
        int r = idx >> 4, d4 = (idx & 15) << 2;
        float4 v = *(const float4*)&Qg[r * 64 + d4];
        Qs[r * 65 + d4 + 0] = v.x * 0.125f;
        Qs[r * 65 + d4 + 1] = v.y * 0.125f;
        Qs[r * 65 + d4 + 2] = v.z * 0.125f;
        Qs[r * 65 + d4 + 3] = v.w * 0.125f;
    }

    float m_r[4], l_r[4], o[4][4];
#pragma unroll
    for (int r = 0; r < 4; r++) {
        m_r[r] = -1e30f; l_r[r] = 0.f;
#pragma unroll
        for (int c = 0; c < 4; c++) o[r][c] = 0.f;
    }

    for (int j = 0; j <= qt; j++) {
        const float* Kg = Kall + ((size_t)bh * Tx + j * 64) * HDx;
        const float* Vg = Vall + ((size_t)bh * Tx + j * 64) * HDx;
#pragma unroll
        for (int i = 0; i < 4; i++) {
            int idx = i * 256 + tid;
            int r = idx >> 4, d4 = (idx & 15) << 2;
            float4 kv = *(const float4*)&Kg[r * 64 + d4];
            Ks[r * 65 + d4 + 0] = kv.x; Ks[r * 65 + d4 + 1] = kv.y;
            Ks[r * 65 + d4 + 2] = kv.z; Ks[r * 65 + d4 + 3] = kv.w;
            float4 vv = *(const float4*)&Vg[r * 64 + d4];
            *(float4*)&Vs[r * 64 + d4] = vv;
        }
        __syncthreads();

        // S = Q K^T
        float s[4][4];
#pragma unroll
        for (int r = 0; r < 4; r++)
#pragma unroll
            for (int c = 0; c < 4; c++) s[r][c] = 0.f;

#pragma unroll 8
        for (int d = 0; d < 64; d++) {
            float qf[4], kf[4];
#pragma unroll
            for (int r = 0; r < 4; r++) qf[r] = Qs[(ty * 4 + r) * 65 + d];
#pragma unroll
            for (int c = 0; c < 4; c++) kf[c] = Ks[(tx * 4 + c) * 65 + d];
#pragma unroll
            for (int r = 0; r < 4; r++)
#pragma unroll
                for (int c = 0; c < 4; c++) s[r][c] += qf[r] * kf[c];
        }

        if (j == qt) {  // causal mask on diagonal tile
#pragma unroll
            for (int r = 0; r < 4; r++)
#pragma unroll
                for (int c = 0; c < 4; c++)
                    if (tx * 4 + c > ty * 4 + r) s[r][c] = -1e30f;
        }

        // Online softmax update
#pragma unroll
        for (int r = 0; r < 4; r++) {
            float mx = fmaxf(fmaxf(s[r][0], s[r][1]), fmaxf(s[r][2], s[r][3]));
#pragma unroll
            for (int off = 8; off; off >>= 1)
                mx = fmaxf(mx, __shfl_xor_sync(0xffffffffu, mx, off));
            float mnew = fmaxf(m_r[r], mx);
            float alpha = __expf(m_r[r] - mnew);
            m_r[r] = mnew;
            float rs = 0.f;
#pragma unroll
            for (int c = 0; c < 4; c++) {
                float p = __expf(s[r][c] - mnew);
                Ps[(ty * 4 + r) * 65 + tx * 4 + c] = p;
                rs += p;
            }
#pragma unroll
            for (int off = 8; off; off >>= 1)
                rs += __shfl_xor_sync(0xffffffffu, rs, off);
            l_r[r] = l_r[r] * alpha + rs;
#pragma unroll
            for (int c = 0; c < 4; c++) o[r][c] *= alpha;
        }
        __syncthreads();

        // O += P V
#pragma unroll 8
        for (int k = 0; k < 64; k++) {
            float pf[4];
#pragma unroll
            for (int r = 0; r < 4; r++) pf[r] = Ps[(ty * 4 + r) * 65 + k];
            float4 vv = *(float4*)&Vs[k * 64 + tx * 4];
#pragma unroll
            for (int r = 0; r < 4; r++) {
                o[r][0] += pf[r] * vv.x;
                o[r][1] += pf[r] * vv.y;
                o[r][2] += pf[r] * vv.z;
                o[r][3] += pf[r] * vv.w;
            }
        }
        __syncthreads();
    }

    // Write [b, t, h*64+d]
    int bb = bh >> 4, h = bh & 15;
#pragma unroll
    for (int r = 0; r < 4; r++) {
        float inv = 1.0f / l_r[r];
        int t = qt * 64 + ty * 4 + r;
        float4 ov = make_float4(o[r][0] * inv, o[r][1] * inv,
                                o[r][2] * inv, o[r][3] * inv);
        *(float4*)&g_atto[((size_t)bb * Tx + t) * Cx + h * 64 + tx * 4] = ov;
    }
}

// ---------------------------------------------------------------------------
extern "C" void kernel_launch(void* const* d_in, const int* in_sizes, int n_in,
                              void* d_out, int out_size)
{
    const float* x      = (const float*)d_in[0];
    const float* W_attn = (const float*)d_in[1];
    const float* b_attn = (const float*)d_in[2];
    const float* W_proj = (const float*)d_in[3];
    const float* b_proj = (const float*)d_in[4];

    float* y    = (float*)d_out;                      // [B,T,C]
    float* kout = y + (size_t)Bx * Tx * Cx;           // [B,H,T,hd]
    float* vout = kout + (size_t)Bx * Hx * Tx * HDx;  // [B,H,T,hd]

    cudaFuncSetAttribute(attn_kernel,
                         cudaFuncAttributeMaxDynamicSharedMemorySize,
                         ATTN_SMEM_BYTES);

    gemm_qkv_kernel<<<dim3(N_QKV / 128, Mx / 128), 256>>>(x, W_attn, b_attn, kout, vout);
    attn_kernel<<<dim3(Tx / 64, Bx * Hx), 256, ATTN_SMEM_BYTES>>>(kout, vout);
    gemm_proj_kernel<<<dim3(Cx / 128, Mx / 128), 256>>>(W_proj, b_proj, y);
}

// round 3
// speedup vs baseline: 2.5447x; 2.5447x over previous
#include <cuda_runtime.h>

// Problem constants
#define Bx 2
#define Tx 2048
#define Cx 1024
#define Hx 16
#define HDx 64
#define Mx (Bx*Tx)          // 4096
#define N_QKV (3*Cx)        // 3072

// Scratch (device globals: allocation-free per harness rules)
__device__ float g_qbuf[(size_t)Bx*Hx*Tx*HDx];   // q in [B,H,T,hd]
__device__ float g_atto[(size_t)Bx*Tx*Cx];       // attention out [B,T,C]

// ---------------------------------------------------------------------------
// tf32 helpers
// ---------------------------------------------------------------------------
__device__ __forceinline__ unsigned f2tf(float x) {
    unsigned u;
    asm("cvt.rna.tf32.f32 %0, %1;" : "=r"(u) : "f"(x));
    return u;
}

__device__ __forceinline__ void mma8(float* c, const unsigned* a, const unsigned* b) {
    asm volatile(
        "mma.sync.aligned.m16n8k8.row.col.f32.tf32.tf32.f32 "
        "{%0,%1,%2,%3},{%4,%5,%6,%7},{%8,%9},{%0,%1,%2,%3};\n"
        : "+f"(c[0]), "+f"(c[1]), "+f"(c[2]), "+f"(c[3])
        : "r"(a[0]), "r"(a[1]), "r"(a[2]), "r"(a[3]), "r"(b[0]), "r"(b[1]));
}

// ---------------------------------------------------------------------------
// Tensor-core GEMM: out = A[M,K] @ W[K,NN] + bias.
// Block 128x128, K-chunk 32, 8 warps (2m x 4n), warp tile 64x32.
// QKV=true: A = Ain (x), scatter epilogue (q->g_qbuf, k->kout, v->vout).
// QKV=false: A = g_atto (device global, resolved in device code!), write Y.
// ---------------------------------------------------------------------------
template <int NN, bool QKV>
__global__ __launch_bounds__(256) void gemm_tc_kernel(
    const float* __restrict__ Ain, const float* __restrict__ W,
    const float* __restrict__ bias,
    float* __restrict__ Y, float* __restrict__ kout, float* __restrict__ vout)
{
    const int K = Cx;
    const float* A = QKV ? Ain : (const float*)g_atto;   // device-side symbol ref

    __shared__ unsigned As[128 * 36];   // [m][k], stride 36 (4 mod 32)
    __shared__ unsigned Bs[32 * 136];   // [k][n], stride 136 (8 mod 32)

    int tid = threadIdx.x;
    int lane = tid & 31;
    int w = tid >> 5;
    int wm = w >> 2;          // 0..1
    int wn = w & 3;           // 0..3
    int row0 = blockIdx.y * 128;
    int col0 = blockIdx.x * 128;

    float acc[4][4][4];
#pragma unroll
    for (int mt = 0; mt < 4; mt++)
#pragma unroll
        for (int nt = 0; nt < 4; nt++)
#pragma unroll
            for (int e = 0; e < 4; e++) acc[mt][nt][e] = 0.f;

    for (int k0 = 0; k0 < K; k0 += 32) {
        // Load A panel: 128x32 floats = 1024 float4
#pragma unroll
        for (int i = 0; i < 4; i++) {
            int f = i * 256 + tid;
            int r = f >> 3, k4 = (f & 7) << 2;
            float4 v = *(const float4*)&A[(size_t)(row0 + r) * K + k0 + k4];
            uint4 u = make_uint4(f2tf(v.x), f2tf(v.y), f2tf(v.z), f2tf(v.w));
            *(uint4*)&As[r * 36 + k4] = u;
        }
        // Load B panel: 32x128 floats
#pragma unroll
        for (int i = 0; i < 4; i++) {
            int f = i * 256 + tid;
            int kr = f >> 5, n4 = (f & 31) << 2;
            float4 v = *(const float4*)&W[(size_t)(k0 + kr) * NN + col0 + n4];
            uint4 u = make_uint4(f2tf(v.x), f2tf(v.y), f2tf(v.z), f2tf(v.w));
            *(uint4*)&Bs[kr * 136 + n4] = u;
        }
        __syncthreads();

#pragma unroll
        for (int ks = 0; ks < 4; ks++) {
            unsigned a[4][4], b[4][2];
#pragma unroll
            for (int mt = 0; mt < 4; mt++) {
                int r = wm * 64 + mt * 16 + (lane >> 2);
                int c = ks * 8 + (lane & 3);
                a[mt][0] = As[r * 36 + c];
                a[mt][1] = As[(r + 8) * 36 + c];
                a[mt][2] = As[r * 36 + c + 4];
                a[mt][3] = As[(r + 8) * 36 + c + 4];
            }
#pragma unroll
            for (int nt = 0; nt < 4; nt++) {
                int br = ks * 8 + (lane & 3);
                int bc = wn * 32 + nt * 8 + (lane >> 2);
                b[nt][0] = Bs[br * 136 + bc];
                b[nt][1] = Bs[(br + 4) * 136 + bc];
            }
#pragma unroll
            for (int mt = 0; mt < 4; mt++)
#pragma unroll
                for (int nt = 0; nt < 4; nt++)
                    mma8(acc[mt][nt], a[mt], b[nt]);
        }
        __syncthreads();
    }

    // Epilogue
#pragma unroll
    for (int mt = 0; mt < 4; mt++) {
#pragma unroll
        for (int e2 = 0; e2 < 2; e2++) {   // row half (e>=2 -> +8)
            int r = row0 + wm * 64 + mt * 16 + (lane >> 2) + e2 * 8;
#pragma unroll
            for (int nt = 0; nt < 4; nt++) {
                int c = col0 + wn * 32 + nt * 8 + (lane & 3) * 2;
                float v0 = acc[mt][nt][e2 * 2 + 0] + bias[c];
                float v1 = acc[mt][nt][e2 * 2 + 1] + bias[c + 1];
                if (QKV) {
                    int bb = r >> 11, t = r & 2047;
                    // c and c+1 stay within same section/head (c even, hd=64)
                    int sec = c >> 10;
                    int within = c & 1023;
                    int h = within >> 6, d = within & 63;
                    size_t idx = ((((size_t)bb * Hx + h) * Tx) + t) * HDx + d;
                    float* dst = (sec == 0) ? g_qbuf : (sec == 1) ? kout : vout;
                    dst[idx] = v0;
                    dst[idx + 1] = v1;
                } else {
                    *(float2*)&Y[(size_t)r * NN + c] = make_float2(v0, v1);
                }
            }
        }
    }
}

// ---------------------------------------------------------------------------
// Flash attention (causal) with tensor-core mma.
// Grid (32 qtiles, 32 bh), 256 threads = 8 warps (4m x 2n), 64x64 tiles.
// Softmax routed through smem; O accumulators live in mma C fragments.
// ---------------------------------------------------------------------------
#define QS_STRIDE 68
#define VS_STRIDE 72
#define ATTN_SMEM_WORDS (64*QS_STRIDE*3 + 64*VS_STRIDE + 128)
#define ATTN_SMEM_BYTES (ATTN_SMEM_WORDS * 4)

__global__ __launch_bounds__(256) void attn_tc_kernel(
    const float* __restrict__ Kall, const float* __restrict__ Vall)
{
    extern __shared__ unsigned smu[];
    unsigned* Qs = smu;                        // [64][68] tf32
    unsigned* Ks = Qs + 64 * QS_STRIDE;        // [64][68] tf32
    unsigned* Ssu = Ks + 64 * QS_STRIDE;       // [64][68] fp32 S then tf32 P
    unsigned* Vs = Ssu + 64 * QS_STRIDE;       // [64][72] tf32
    float* Ssf = (float*)Ssu;
    float* alpha_s = (float*)(Vs + 64 * VS_STRIDE);  // [64]
    float* l_s = alpha_s + 64;                       // [64]

    int tid = threadIdx.x;
    int lane = tid & 31;
    int w = tid >> 5;
    int wm = w >> 1;          // 0..3
    int wn = w & 1;           // 0..1
    int qt = blockIdx.x, bh = blockIdx.y;

    // Softmax ownership
    int srow = tid >> 2;      // 0..63
    int sg = tid & 3;         // col block 16*sg

    const float* Qg = g_qbuf + ((size_t)bh * Tx + qt * 64) * HDx;

    // Load Q (scaled 1/sqrt(64)), convert to tf32
#pragma unroll
    for (int i = 0; i < 4; i++) {
        int f = i * 256 + tid;
        int r = f >> 4, d4 = (f & 15) << 2;
        float4 v = *(const float4*)&Qg[r * 64 + d4];
        uint4 u = make_uint4(f2tf(v.x * 0.125f), f2tf(v.y * 0.125f),
                             f2tf(v.z * 0.125f), f2tf(v.w * 0.125f));
        *(uint4*)&Qs[r * QS_STRIDE + d4] = u;
    }

    float o[4][4];
#pragma unroll
    for (int nt = 0; nt < 4; nt++)
#pragma unroll
        for (int e = 0; e < 4; e++) o[nt][e] = 0.f;
    float m_r = -1e30f, l_r = 0.f;

    for (int j = 0; j <= qt; j++) {
        const float* Kg = Kall + ((size_t)bh * Tx + j * 64) * HDx;
        const float* Vg = Vall + ((size_t)bh * Tx + j * 64) * HDx;
#pragma unroll
        for (int i = 0; i < 4; i++) {
            int f = i * 256 + tid;
            int r = f >> 4, d4 = (f & 15) << 2;
            float4 kv = *(const float4*)&Kg[r * 64 + d4];
            *(uint4*)&Ks[r * QS_STRIDE + d4] =
                make_uint4(f2tf(kv.x), f2tf(kv.y), f2tf(kv.z), f2tf(kv.w));
            float4 vv = *(const float4*)&Vg[r * 64 + d4];
            *(uint4*)&Vs[r * VS_STRIDE + d4] =
                make_uint4(f2tf(vv.x), f2tf(vv.y), f2tf(vv.z), f2tf(vv.w));
        }
        __syncthreads();

        // S = Q K^T  (warp tile 16x32)
        float s[4][4];
#pragma unroll
        for (int nt = 0; nt < 4; nt++)
#pragma unroll
            for (int e = 0; e < 4; e++) s[nt][e] = 0.f;

#pragma unroll
        for (int ks = 0; ks < 8; ks++) {
            unsigned a[4], b[4][2];
            int r = wm * 16 + (lane >> 2);
            int c = ks * 8 + (lane & 3);
            a[0] = Qs[r * QS_STRIDE + c];
            a[1] = Qs[(r + 8) * QS_STRIDE + c];
            a[2] = Qs[r * QS_STRIDE + c + 4];
            a[3] = Qs[(r + 8) * QS_STRIDE + c + 4];
#pragma unroll
            for (int nt = 0; nt < 4; nt++) {
                int tok = wn * 32 + nt * 8 + (lane >> 2);
                int dim = ks * 8 + (lane & 3);
                b[nt][0] = Ks[tok * QS_STRIDE + dim];
                b[nt][1] = Ks[tok * QS_STRIDE + dim + 4];
            }
#pragma unroll
            for (int nt = 0; nt < 4; nt++) mma8(s[nt], a, b[nt]);
        }

        // Store S fragments to smem
#pragma unroll
        for (int nt = 0; nt < 4; nt++) {
            int r = wm * 16 + (lane >> 2);
            int c = wn * 32 + nt * 8 + (lane & 3) * 2;
            Ssf[r * QS_STRIDE + c] = s[nt][0];
            Ssf[r * QS_STRIDE + c + 1] = s[nt][1];
            Ssf[(r + 8) * QS_STRIDE + c] = s[nt][2];
            Ssf[(r + 8) * QS_STRIDE + c + 1] = s[nt][3];
        }
        __syncthreads();

        // Row softmax: thread (srow, sg) handles cols [16*sg, 16*sg+16)
        {
            float vbuf[16];
#pragma unroll
            for (int q4 = 0; q4 < 4; q4++) {
                float4 v = *(float4*)&Ssf[srow * QS_STRIDE + sg * 16 + q4 * 4];
                vbuf[q4 * 4 + 0] = v.x; vbuf[q4 * 4 + 1] = v.y;
                vbuf[q4 * 4 + 2] = v.z; vbuf[q4 * 4 + 3] = v.w;
            }
            if (j == qt) {
#pragma unroll
                for (int k = 0; k < 16; k++)
                    if (sg * 16 + k > srow) vbuf[k] = -1e30f;
            }
            float mx = vbuf[0];
#pragma unroll
            for (int k = 1; k < 16; k++) mx = fmaxf(mx, vbuf[k]);
            mx = fmaxf(mx, __shfl_xor_sync(0xffffffffu, mx, 1));
            mx = fmaxf(mx, __shfl_xor_sync(0xffffffffu, mx, 2));
            float mnew = fmaxf(m_r, mx);
            float alpha = __expf(m_r - mnew);
            float rs = 0.f;
#pragma unroll
            for (int k = 0; k < 16; k++) {
                float p = __expf(vbuf[k] - mnew);
                rs += p;
                Ssu[srow * QS_STRIDE + sg * 16 + k] = f2tf(p);
            }
            rs += __shfl_xor_sync(0xffffffffu, rs, 1);
            rs += __shfl_xor_sync(0xffffffffu, rs, 2);
            l_r = l_r * alpha + rs;
            m_r = mnew;
            if (sg == 0) alpha_s[srow] = alpha;
        }
        __syncthreads();

        // Scale O fragments by per-row alpha
        {
            int r0 = wm * 16 + (lane >> 2);
            float al0 = alpha_s[r0];
            float al1 = alpha_s[r0 + 8];
#pragma unroll
            for (int nt = 0; nt < 4; nt++) {
                o[nt][0] *= al0; o[nt][1] *= al0;
                o[nt][2] *= al1; o[nt][3] *= al1;
            }
        }

        // O += P V
#pragma unroll
        for (int ks = 0; ks < 8; ks++) {
            unsigned a[4], b[4][2];
            int r = wm * 16 + (lane >> 2);
            int c = ks * 8 + (lane & 3);
            a[0] = Ssu[r * QS_STRIDE + c];
            a[1] = Ssu[(r + 8) * QS_STRIDE + c];
            a[2] = Ssu[r * QS_STRIDE + c + 4];
            a[3] = Ssu[(r + 8) * QS_STRIDE + c + 4];
#pragma unroll
            for (int nt = 0; nt < 4; nt++) {
                int tok = ks * 8 + (lane & 3);
                int dim = wn * 32 + nt * 8 + (lane >> 2);
                b[nt][0] = Vs[tok * VS_STRIDE + dim];
                b[nt][1] = Vs[(tok + 4) * VS_STRIDE + dim];
            }
#pragma unroll
            for (int nt = 0; nt < 4; nt++) mma8(o[nt], a, b[nt]);
        }
        __syncthreads();
    }

    // Final l broadcast
    if (sg == 0) l_s[srow] = l_r;
    __syncthreads();

    int bb = bh >> 4, h = bh & 15;
    int r0 = wm * 16 + (lane >> 2);
    float inv0 = 1.0f / l_s[r0];
    float inv1 = 1.0f / l_s[r0 + 8];
#pragma unroll
    for (int nt = 0; nt < 4; nt++) {
        int c = wn * 32 + nt * 8 + (lane & 3) * 2;
        int t0 = qt * 64 + r0;
        *(float2*)&g_atto[((size_t)bb * Tx + t0) * Cx + h * 64 + c] =
            make_float2(o[nt][0] * inv0, o[nt][1] * inv0);
        *(float2*)&g_atto[((size_t)bb * Tx + t0 + 8) * Cx + h * 64 + c] =
            make_float2(o[nt][2] * inv1, o[nt][3] * inv1);
    }
}

// ---------------------------------------------------------------------------
extern "C" void kernel_launch(void* const* d_in, const int* in_sizes, int n_in,
                              void* d_out, int out_size)
{
    const float* x      = (const float*)d_in[0];
    const float* W_attn = (const float*)d_in[1];
    const float* b_attn = (const float*)d_in[2];
    const float* W_proj = (const float*)d_in[3];
    const float* b_proj = (const float*)d_in[4];

    float* y    = (float*)d_out;                      // [B,T,C]
    float* kout = y + (size_t)Bx * Tx * Cx;           // [B,H,T,hd]
    float* vout = kout + (size_t)Bx * Hx * Tx * HDx;  // [B,H,T,hd]

    cudaFuncSetAttribute(attn_tc_kernel,
                         cudaFuncAttributeMaxDynamicSharedMemorySize,
                         ATTN_SMEM_BYTES);

    gemm_tc_kernel<N_QKV, true><<<dim3(N_QKV / 128, Mx / 128), 256>>>(
        x, W_attn, b_attn, nullptr, kout, vout);
    attn_tc_kernel<<<dim3(Tx / 64, Bx * Hx), 256, ATTN_SMEM_BYTES>>>(kout, vout);
    gemm_tc_kernel<Cx, false><<<dim3(Cx / 128, Mx / 128), 256>>>(
        nullptr, W_proj, b_proj, y, nullptr, nullptr);   // A = g_atto (device-side)
}

// round 5
// speedup vs baseline: 3.2949x; 1.2948x over previous
#include <cuda_runtime.h>
#include <cuda_fp16.h>
#include <cstdint>

// Problem constants
#define Bx 2
#define Tx 2048
#define Cx 1024
#define Hx 16
#define HDx 64
#define Mx (Bx*Tx)          // 4096
#define N_QKV (3*Cx)        // 3072

// fp16 scratch (device globals: allocation-free per harness rules)
__device__ __half g_xh[(size_t)Mx*Cx];
__device__ __half g_wah[(size_t)Cx*N_QKV];
__device__ __half g_wph[(size_t)Cx*Cx];
__device__ __half g_qh[(size_t)Bx*Hx*Tx*HDx];    // pre-scaled by 0.125
__device__ __half g_kh[(size_t)Bx*Hx*Tx*HDx];
__device__ __half g_vh[(size_t)Bx*Hx*Tx*HDx];
__device__ __half g_attoh[(size_t)Bx*Tx*Cx];

// ---------------------------------------------------------------------------
// helpers
// ---------------------------------------------------------------------------
__device__ __forceinline__ void mma16(float* c, const unsigned* a, const unsigned* b) {
    asm volatile(
        "mma.sync.aligned.m16n8k16.row.col.f32.f16.f16.f32 "
        "{%0,%1,%2,%3},{%4,%5,%6,%7},{%8,%9},{%0,%1,%2,%3};\n"
        : "+f"(c[0]), "+f"(c[1]), "+f"(c[2]), "+f"(c[3])
        : "r"(a[0]), "r"(a[1]), "r"(a[2]), "r"(a[3]), "r"(b[0]), "r"(b[1]));
}

__device__ __forceinline__ void ldsm4(unsigned& r0, unsigned& r1, unsigned& r2,
                                      unsigned& r3, const __half* p) {
    unsigned a = (unsigned)__cvta_generic_to_shared(p);
    asm volatile("ldmatrix.sync.aligned.m8n8.x4.shared.b16 {%0,%1,%2,%3},[%4];\n"
                 : "=r"(r0), "=r"(r1), "=r"(r2), "=r"(r3) : "r"(a));
}

__device__ __forceinline__ void ldsm4t(unsigned& r0, unsigned& r1, unsigned& r2,
                                       unsigned& r3, const __half* p) {
    unsigned a = (unsigned)__cvta_generic_to_shared(p);
    asm volatile("ldmatrix.sync.aligned.m8n8.x4.trans.shared.b16 {%0,%1,%2,%3},[%4];\n"
                 : "=r"(r0), "=r"(r1), "=r"(r2), "=r"(r3) : "r"(a));
}

__device__ __forceinline__ void cpa16(const __half* gptr, __half* sptr) {
    unsigned d = (unsigned)__cvta_generic_to_shared(sptr);
    asm volatile("cp.async.cg.shared.global [%0], [%1], 16;\n" :: "r"(d), "l"(gptr));
}
#define CPA_COMMIT() asm volatile("cp.async.commit_group;\n")
#define CPA_WAIT1()  asm volatile("cp.async.wait_group 1;\n" ::: "memory")

// ---------------------------------------------------------------------------
// fp32 -> fp16 conversion pre-pass (x, W_attn, W_proj)
// ---------------------------------------------------------------------------
__global__ __launch_bounds__(256) void convert_inputs_kernel(
    const float* __restrict__ x, const float* __restrict__ wa,
    const float* __restrict__ wp)
{
    const int X4 = Mx * Cx / 4, WA4 = Cx * N_QKV / 4, WP4 = Cx * Cx / 4;
    int i = blockIdx.x * blockDim.x + threadIdx.x;
    const float* src; __half* dst; int off;
    if (i < X4)                 { src = x;  dst = g_xh;  off = i; }
    else if (i < X4 + WA4)      { src = wa; dst = g_wah; off = i - X4; }
    else if (i < X4 + WA4 + WP4){ src = wp; dst = g_wph; off = i - X4 - WA4; }
    else return;
    float4 v = *(const float4*)&src[(size_t)off * 4];
    *(__half2*)&dst[(size_t)off * 4]     = __floats2half2_rn(v.x, v.y);
    *(__half2*)&dst[(size_t)off * 4 + 2] = __floats2half2_rn(v.z, v.w);
}

// ---------------------------------------------------------------------------
// fp16 tensor-core GEMM with cp.async double buffering.
// Block 128x128, k-chunk 64, 8 warps (2m x 4n), warp tile 64x32, m16n8k16.
// QKV=true:  A=g_xh, W=g_wah; scatter epilogue (q->g_qh*0.125, k/v->fp32 out + half scratch)
// QKV=false: A=g_attoh, W=g_wph; Y = A@W + bias (fp32)
// ---------------------------------------------------------------------------
#define LDA 72      // 64 + 8 pad (halves)
#define LDB 136     // 128 + 8 pad (halves)
#define ASTG (128*LDA)
#define BSTG (64*LDB)
#define GEMM_SMEM ((2*ASTG + 2*BSTG) * 2)   // bytes = 71680

template <int NN, bool QKV>
__global__ __launch_bounds__(256, 2) void gemm_h_kernel(
    const float* __restrict__ bias, float* __restrict__ Y,
    float* __restrict__ kout, float* __restrict__ vout)
{
    const int K = Cx;
    const __half* A = QKV ? g_xh : g_attoh;
    const __half* W = QKV ? g_wah : g_wph;

    extern __shared__ __half sh[];
    __half* As = sh;               // [2][128][LDA]
    __half* Bs = sh + 2 * ASTG;    // [2][64][LDB]

    int tid = threadIdx.x, lane = tid & 31, w = tid >> 5;
    int wm = w >> 2, wn = w & 3;
    int row0 = blockIdx.y * 128, col0 = blockIdx.x * 128;

    auto issue = [&](int s) {
        int buf = s & 1;
        const __half* gA = A + (size_t)row0 * K + s * 64;
#pragma unroll
        for (int i = 0; i < 4; i++) {
            int c = i * 256 + tid;
            int r = c >> 3, o = (c & 7) * 8;
            cpa16(gA + (size_t)r * K + o, &As[buf * ASTG + r * LDA + o]);
        }
        const __half* gB = W + (size_t)(s * 64) * NN + col0;
#pragma unroll
        for (int i = 0; i < 4; i++) {
            int c = i * 256 + tid;
            int r = c >> 4, o = (c & 15) * 8;
            cpa16(gB + (size_t)r * NN + o, &Bs[buf * BSTG + r * LDB + o]);
        }
    };

    float acc[4][4][4];
#pragma unroll
    for (int mt = 0; mt < 4; mt++)
#pragma unroll
        for (int nt = 0; nt < 4; nt++)
#pragma unroll
            for (int e = 0; e < 4; e++) acc[mt][nt][e] = 0.f;

    issue(0); CPA_COMMIT();
    issue(1); CPA_COMMIT();

    int arow = wm * 64 + (lane & 15);
    int acol = (lane >> 4) * 8;
    int brow = lane & 15;
    int bcol = wn * 32 + (lane >> 4) * 8;

    const int NS = K / 64;   // 16
    for (int s = 0; s < NS; s++) {
        CPA_WAIT1();
        __syncthreads();
        int buf = s & 1;
        const __half* Ab = &As[buf * ASTG];
        const __half* Bb = &Bs[buf * BSTG];
#pragma unroll
        for (int ks = 0; ks < 4; ks++) {
            unsigned af[4][4], bf[2][4];
#pragma unroll
            for (int mt = 0; mt < 4; mt++)
                ldsm4(af[mt][0], af[mt][1], af[mt][2], af[mt][3],
                      &Ab[(arow + mt * 16) * LDA + ks * 16 + acol]);
#pragma unroll
            for (int g = 0; g < 2; g++)
                ldsm4t(bf[g][0], bf[g][1], bf[g][2], bf[g][3],
                       &Bb[(ks * 16 + brow) * LDB + bcol + g * 16]);
#pragma unroll
            for (int mt = 0; mt < 4; mt++)
#pragma unroll
                for (int nt = 0; nt < 4; nt++)
                    mma16(acc[mt][nt], af[mt], &bf[nt >> 1][(nt & 1) * 2]);
        }
        __syncthreads();
        if (s + 2 < NS) issue(s + 2);
        CPA_COMMIT();
    }

    // Epilogue
#pragma unroll
    for (int mt = 0; mt < 4; mt++) {
#pragma unroll
        for (int e2 = 0; e2 < 2; e2++) {
            int r = row0 + wm * 64 + mt * 16 + (lane >> 2) + e2 * 8;
#pragma unroll
            for (int nt = 0; nt < 4; nt++) {
                int c = col0 + wn * 32 + nt * 8 + (lane & 3) * 2;
                float v0 = acc[mt][nt][e2 * 2 + 0] + bias[c];
                float v1 = acc[mt][nt][e2 * 2 + 1] + bias[c + 1];
                if (QKV) {
                    int bb = r >> 11, t = r & 2047;
                    int sec = c >> 10, within = c & 1023;
                    int h = within >> 6, d = within & 63;
                    size_t idx = ((((size_t)bb * Hx + h) * Tx) + t) * HDx + d;
                    if (sec == 0) {
                        *(__half2*)&g_qh[idx] = __floats2half2_rn(v0 * 0.125f, v1 * 0.125f);
                    } else if (sec == 1) {
                        *(float2*)&kout[idx] = make_float2(v0, v1);
                        *(__half2*)&g_kh[idx] = __floats2half2_rn(v0, v1);
                    } else {
                        *(float2*)&vout[idx] = make_float2(v0, v1);
                        *(__half2*)&g_vh[idx] = __floats2half2_rn(v0, v1);
                    }
                } else {
                    *(float2*)&Y[(size_t)r * NN + c] = make_float2(v0, v1);
                }
            }
        }
    }
}

// ---------------------------------------------------------------------------
// fp16 flash attention (causal). Grid (32 qtiles, 32 bh), 8 warps (4m x 2n),
// 64x64 tiles, m16n8k16 mma + LDSM, cp.async double-buffered K/V.
// ---------------------------------------------------------------------------
#define ALD 72                  // halves stride for Q/K/V/P tiles (144 B)
#define SLD 68                  // fp32 stride for S
#define ATTN_SMEM (64*ALD*2 /*Q*/ + 2*64*ALD*2 /*K*/ + 2*64*ALD*2 /*V*/ \
                   + 64*SLD*4 /*S*/ + 64*ALD*2 /*P*/ + 2*64*4 /*alpha,l*/)

__global__ __launch_bounds__(256, 2) void attn_h_kernel()
{
    extern __shared__ char smc[];
    __half* Qh = (__half*)smc;                 // [64][ALD]
    __half* Kh = Qh + 64 * ALD;                // [2][64][ALD]
    __half* Vh = Kh + 2 * 64 * ALD;            // [2][64][ALD]
    float* Ssf = (float*)(Vh + 2 * 64 * ALD);  // [64][SLD]
    __half* Ph = (__half*)(Ssf + 64 * SLD);    // [64][ALD]
    float* alpha_s = (float*)(Ph + 64 * ALD);  // [64]
    float* l_s = alpha_s + 64;                 // [64]

    int tid = threadIdx.x, lane = tid & 31, w = tid >> 5;
    int wm = w >> 1, wn = w & 1;
    int qt = blockIdx.x, bh = blockIdx.y;
    int srow = tid >> 2, sg = tid & 3;

    const __half* Qg = g_qh + ((size_t)bh * Tx + qt * 64) * HDx;
    const __half* Kb0 = g_kh + (size_t)bh * Tx * HDx;
    const __half* Vb0 = g_vh + (size_t)bh * Tx * HDx;

    // Q tile: plain vectorized copy (once)
#pragma unroll
    for (int i = 0; i < 2; i++) {
        int c = i * 256 + tid;
        int r = c >> 3, o = (c & 7) * 8;
        *(uint4*)&Qh[r * ALD + o] = *(const uint4*)&Qg[r * HDx + o];
    }

    auto issue_kv = [&](int j) {
        int buf = j & 1;
        const __half* Kg = Kb0 + (size_t)j * 64 * HDx;
        const __half* Vg = Vb0 + (size_t)j * 64 * HDx;
#pragma unroll
        for (int i = 0; i < 2; i++) {
            int c = i * 256 + tid;
            int r = c >> 3, o = (c & 7) * 8;
            cpa16(Kg + (size_t)r * HDx + o, &Kh[(buf * 64 + r) * ALD + o]);
            cpa16(Vg + (size_t)r * HDx + o, &Vh[(buf * 64 + r) * ALD + o]);
        }
    };

    issue_kv(0); CPA_COMMIT();
    if (qt >= 1) issue_kv(1);
    CPA_COMMIT();

    float o[4][4];
#pragma unroll
    for (int nt = 0; nt < 4; nt++)
#pragma unroll
        for (int e = 0; e < 4; e++) o[nt][e] = 0.f;
    float m_r = -1e30f, l_r = 0.f;

    int arow = wm * 16 + (lane & 15);
    int acol = (lane >> 4) * 8;
    int krow = (lane >> 4) * 8 + (lane & 7);   // non-trans B (K)
    int kcol = ((lane >> 3) & 1) * 8;
    int vrow = lane & 15;                      // trans B (V)
    int vcol = wn * 32 + (lane >> 4) * 8;

    for (int j = 0; j <= qt; j++) {
        CPA_WAIT1();
        __syncthreads();
        int buf = j & 1;
        const __half* Kb = &Kh[buf * 64 * ALD];
        const __half* Vb = &Vh[buf * 64 * ALD];

        // S = Q K^T   (warp tile 16 q x 32 tok)
        float s[4][4];
#pragma unroll
        for (int nt = 0; nt < 4; nt++)
#pragma unroll
            for (int e = 0; e < 4; e++) s[nt][e] = 0.f;

#pragma unroll
        for (int ks = 0; ks < 4; ks++) {       // d dimension, k16 steps
            unsigned af[4], bf[2][4];
            ldsm4(af[0], af[1], af[2], af[3],
                  &Qh[arow * ALD + ks * 16 + acol]);
#pragma unroll
            for (int g = 0; g < 2; g++)
                ldsm4(bf[g][0], bf[g][1], bf[g][2], bf[g][3],
                      &Kb[(wn * 32 + g * 16 + krow) * ALD + ks * 16 + kcol]);
#pragma unroll
            for (int nt = 0; nt < 4; nt++)
                mma16(s[nt], af, &bf[nt >> 1][(nt & 1) * 2]);
        }

        // S fragments -> smem
#pragma unroll
        for (int nt = 0; nt < 4; nt++) {
            int r = wm * 16 + (lane >> 2);
            int c = wn * 32 + nt * 8 + (lane & 3) * 2;
            Ssf[r * SLD + c]     = s[nt][0];
            Ssf[r * SLD + c + 1] = s[nt][1];
            Ssf[(r + 8) * SLD + c]     = s[nt][2];
            Ssf[(r + 8) * SLD + c + 1] = s[nt][3];
        }
        __syncthreads();

        // Row softmax: thread (srow, sg) owns cols [16sg, 16sg+16)
        {
            float vbuf[16];
#pragma unroll
            for (int q4 = 0; q4 < 4; q4++) {
                float4 v = *(float4*)&Ssf[srow * SLD + sg * 16 + q4 * 4];
                vbuf[q4 * 4 + 0] = v.x; vbuf[q4 * 4 + 1] = v.y;
                vbuf[q4 * 4 + 2] = v.z; vbuf[q4 * 4 + 3] = v.w;
            }
            if (j == qt) {
#pragma unroll
                for (int k = 0; k < 16; k++)
                    if (sg * 16 + k > srow) vbuf[k] = -1e30f;
            }
            float mx = vbuf[0];
#pragma unroll
            for (int k = 1; k < 16; k++) mx = fmaxf(mx, vbuf[k]);
            mx = fmaxf(mx, __shfl_xor_sync(0xffffffffu, mx, 1));
            mx = fmaxf(mx, __shfl_xor_sync(0xffffffffu, mx, 2));
            float mnew = fmaxf(m_r, mx);
            float alpha = __expf(m_r - mnew);
            float rs = 0.f;
#pragma unroll
            for (int k = 0; k < 8; k++) {
                float p0 = __expf(vbuf[2 * k] - mnew);
                float p1 = __expf(vbuf[2 * k + 1] - mnew);
                rs += p0 + p1;
                *(__half2*)&Ph[srow * ALD + sg * 16 + 2 * k] = __floats2half2_rn(p0, p1);
            }
            rs += __shfl_xor_sync(0xffffffffu, rs, 1);
            rs += __shfl_xor_sync(0xffffffffu, rs, 2);
            l_r = l_r * alpha + rs;
            m_r = mnew;
            if (sg == 0) alpha_s[srow] = alpha;
        }
        __syncthreads();

        // O *= alpha ; O += P V
        {
            int r0 = wm * 16 + (lane >> 2);
            float al0 = alpha_s[r0];
            float al1 = alpha_s[r0 + 8];
#pragma unroll
            for (int nt = 0; nt < 4; nt++) {
                o[nt][0] *= al0; o[nt][1] *= al0;
                o[nt][2] *= al1; o[nt][3] *= al1;
            }
        }
#pragma unroll
        for (int ks = 0; ks < 4; ks++) {       // tok dimension
            unsigned af[4], bf[2][4];
            ldsm4(af[0], af[1], af[2], af[3],
                  &Ph[arow * ALD + ks * 16 + acol]);
#pragma unroll
            for (int g = 0; g < 2; g++)
                ldsm4t(bf[g][0], bf[g][1], bf[g][2], bf[g][3],
                       &Vb[(ks * 16 + vrow) * ALD + vcol + g * 16]);
#pragma unroll
            for (int nt = 0; nt < 4; nt++)
                mma16(o[nt], af, &bf[nt >> 1][(nt & 1) * 2]);
        }
        __syncthreads();
        if (j + 2 <= qt) issue_kv(j + 2);
        CPA_COMMIT();
    }

    if (sg == 0) l_s[srow] = l_r;
    __syncthreads();

    int bb = bh >> 4, h = bh & 15;
    int r0 = wm * 16 + (lane >> 2);
    float inv0 = 1.0f / l_s[r0];
    float inv1 = 1.0f / l_s[r0 + 8];
#pragma unroll
    for (int nt = 0; nt < 4; nt++) {
        int c = wn * 32 + nt * 8 + (lane & 3) * 2;
        int t0 = qt * 64 + r0;
        *(__half2*)&g_attoh[((size_t)bb * Tx + t0) * Cx + h * 64 + c] =
            __floats2half2_rn(o[nt][0] * inv0, o[nt][1] * inv0);
        *(__half2*)&g_attoh[((size_t)bb * Tx + t0 + 8) * Cx + h * 64 + c] =
            __floats2half2_rn(o[nt][2] * inv1, o[nt][3] * inv1);
    }
}

// ---------------------------------------------------------------------------
extern "C" void kernel_launch(void* const* d_in, const int* in_sizes, int n_in,
                              void* d_out, int out_size)
{
    const float* x      = (const float*)d_in[0];
    const float* W_attn = (const float*)d_in[1];
    const float* b_attn = (const float*)d_in[2];
    const float* W_proj = (const float*)d_in[3];
    const float* b_proj = (const float*)d_in[4];

    float* y    = (float*)d_out;
    float* kout = y + (size_t)Bx * Tx * Cx;
    float* vout = kout + (size_t)Bx * Hx * Tx * HDx;

    cudaFuncSetAttribute(gemm_h_kernel<N_QKV, true>,
                         cudaFuncAttributeMaxDynamicSharedMemorySize, GEMM_SMEM);
    cudaFuncSetAttribute(gemm_h_kernel<Cx, false>,
                         cudaFuncAttributeMaxDynamicSharedMemorySize, GEMM_SMEM);
    cudaFuncSetAttribute(attn_h_kernel,
                         cudaFuncAttributeMaxDynamicSharedMemorySize, ATTN_SMEM);

    const int TOT4 = (Mx * Cx + Cx * N_QKV + Cx * Cx) / 4;
    convert_inputs_kernel<<<TOT4 / 256, 256>>>(x, W_attn, W_proj);
    gemm_h_kernel<N_QKV, true><<<dim3(N_QKV / 128, Mx / 128), 256, GEMM_SMEM>>>(
        b_attn, nullptr, kout, vout);
    attn_h_kernel<<<dim3(Tx / 64, Bx * Hx), 256, ATTN_SMEM>>>();
    gemm_h_kernel<Cx, false><<<dim3(Cx / 128, Mx / 128), 256, GEMM_SMEM>>>(
        b_proj, y, nullptr, nullptr);
}

// round 10
// speedup vs baseline: 4.0648x; 1.2337x over previous
#include <cuda_runtime.h>
#include <cuda_fp16.h>
#include <cstdint>

// Problem constants
#define Bx 2
#define Tx 2048
#define Cx 1024
#define Hx 16
#define HDx 64
#define Mx (Bx*Tx)          // 4096
#define N_QKV (3*Cx)        // 3072

// fp16 scratch (device globals: allocation-free per harness rules)
__device__ __half g_xh[(size_t)Mx*Cx];
__device__ __half g_wah[(size_t)Cx*N_QKV];
__device__ __half g_wph[(size_t)Cx*Cx];
__device__ __half g_qh[(size_t)Bx*Hx*Tx*HDx];    // pre-scaled by 0.125
__device__ __half g_kh[(size_t)Bx*Hx*Tx*HDx];
__device__ __half g_vh[(size_t)Bx*Hx*Tx*HDx];
__device__ __half g_attoh[(size_t)Bx*Tx*Cx];

// ---------------------------------------------------------------------------
// helpers
// ---------------------------------------------------------------------------
__device__ __forceinline__ void mma16(float* c, const unsigned* a, const unsigned* b) {
    asm volatile(
        "mma.sync.aligned.m16n8k16.row.col.f32.f16.f16.f32 "
        "{%0,%1,%2,%3},{%4,%5,%6,%7},{%8,%9},{%0,%1,%2,%3};\n"
        : "+f"(c[0]), "+f"(c[1]), "+f"(c[2]), "+f"(c[3])
        : "r"(a[0]), "r"(a[1]), "r"(a[2]), "r"(a[3]), "r"(b[0]), "r"(b[1]));
}

__device__ __forceinline__ void ldsm4(unsigned& r0, unsigned& r1, unsigned& r2,
                                      unsigned& r3, const __half* p) {
    unsigned a = (unsigned)__cvta_generic_to_shared(p);
    asm volatile("ldmatrix.sync.aligned.m8n8.x4.shared.b16 {%0,%1,%2,%3},[%4];\n"
                 : "=r"(r0), "=r"(r1), "=r"(r2), "=r"(r3) : "r"(a));
}

__device__ __forceinline__ void ldsm4t(unsigned& r0, unsigned& r1, unsigned& r2,
                                       unsigned& r3, const __half* p) {
    unsigned a = (unsigned)__cvta_generic_to_shared(p);
    asm volatile("ldmatrix.sync.aligned.m8n8.x4.trans.shared.b16 {%0,%1,%2,%3},[%4];\n"
                 : "=r"(r0), "=r"(r1), "=r"(r2), "=r"(r3) : "r"(a));
}

__device__ __forceinline__ void cpa16(const __half* gptr, __half* sptr) {
    unsigned d = (unsigned)__cvta_generic_to_shared(sptr);
    asm volatile("cp.async.cg.shared.global [%0], [%1], 16;\n" :: "r"(d), "l"(gptr));
}
#define CPA_COMMIT() asm volatile("cp.async.commit_group;\n")
#define CPA_WAIT1()  asm volatile("cp.async.wait_group 1;\n" ::: "memory")

__device__ __forceinline__ unsigned h2u(__half2 h) {
    return *(unsigned*)&h;
}

// ---------------------------------------------------------------------------
// fp32 -> fp16 conversion pre-pass (x, W_attn, W_proj)
// ---------------------------------------------------------------------------
__global__ __launch_bounds__(256) void convert_inputs_kernel(
    const float* __restrict__ x, const float* __restrict__ wa,
    const float* __restrict__ wp)
{
    const int X4 = Mx * Cx / 4, WA4 = Cx * N_QKV / 4, WP4 = Cx * Cx / 4;
    int i = blockIdx.x * blockDim.x + threadIdx.x;
    const float* src; __half* dst; int off;
    if (i < X4)                 { src = x;  dst = g_xh;  off = i; }
    else if (i < X4 + WA4)      { src = wa; dst = g_wah; off = i - X4; }
    else if (i < X4 + WA4 + WP4){ src = wp; dst = g_wph; off = i - X4 - WA4; }
    else return;
    float4 v = *(const float4*)&src[(size_t)off * 4];
    *(__half2*)&dst[(size_t)off * 4]     = __floats2half2_rn(v.x, v.y);
    *(__half2*)&dst[(size_t)off * 4 + 2] = __floats2half2_rn(v.z, v.w);
}

// ---------------------------------------------------------------------------
// fp16 tensor-core GEMM with cp.async double buffering. (unchanged from r5)
// ---------------------------------------------------------------------------
#define LDA 72      // 64 + 8 pad (halves)
#define LDB 136     // 128 + 8 pad (halves)
#define ASTG (128*LDA)
#define BSTG (64*LDB)
#define GEMM_SMEM ((2*ASTG + 2*BSTG) * 2)   // bytes = 71680

template <int NN, bool QKV>
__global__ __launch_bounds__(256, 2) void gemm_h_kernel(
    const float* __restrict__ bias, float* __restrict__ Y,
    float* __restrict__ kout, float* __restrict__ vout)
{
    const int K = Cx;
    const __half* A = QKV ? g_xh : g_attoh;
    const __half* W = QKV ? g_wah : g_wph;

    extern __shared__ __half sh[];
    __half* As = sh;               // [2][128][LDA]
    __half* Bs = sh + 2 * ASTG;    // [2][64][LDB]

    int tid = threadIdx.x, lane = tid & 31, w = tid >> 5;
    int wm = w >> 2, wn = w & 3;
    int row0 = blockIdx.y * 128, col0 = blockIdx.x * 128;

    auto issue = [&](int s) {
        int buf = s & 1;
        const __half* gA = A + (size_t)row0 * K + s * 64;
#pragma unroll
        for (int i = 0; i < 4; i++) {
            int c = i * 256 + tid;
            int r = c >> 3, o = (c & 7) * 8;
            cpa16(gA + (size_t)r * K + o, &As[buf * ASTG + r * LDA + o]);
        }
        const __half* gB = W + (size_t)(s * 64) * NN + col0;
#pragma unroll
        for (int i = 0; i < 4; i++) {
            int c = i * 256 + tid;
            int r = c >> 4, o = (c & 15) * 8;
            cpa16(gB + (size_t)r * NN + o, &Bs[buf * BSTG + r * LDB + o]);
        }
    };

    float acc[4][4][4];
#pragma unroll
    for (int mt = 0; mt < 4; mt++)
#pragma unroll
        for (int nt = 0; nt < 4; nt++)
#pragma unroll
            for (int e = 0; e < 4; e++) acc[mt][nt][e] = 0.f;

    issue(0); CPA_COMMIT();
    issue(1); CPA_COMMIT();

    int arow = wm * 64 + (lane & 15);
    int acol = (lane >> 4) * 8;
    int brow = lane & 15;
    int bcol = wn * 32 + (lane >> 4) * 8;

    const int NS = K / 64;   // 16
    for (int s = 0; s < NS; s++) {
        CPA_WAIT1();
        __syncthreads();
        int buf = s & 1;
        const __half* Ab = &As[buf * ASTG];
        const __half* Bb = &Bs[buf * BSTG];
#pragma unroll
        for (int ks = 0; ks < 4; ks++) {
            unsigned af[4][4], bf[2][4];
#pragma unroll
            for (int mt = 0; mt < 4; mt++)
                ldsm4(af[mt][0], af[mt][1], af[mt][2], af[mt][3],
                      &Ab[(arow + mt * 16) * LDA + ks * 16 + acol]);
#pragma unroll
            for (int g = 0; g < 2; g++)
                ldsm4t(bf[g][0], bf[g][1], bf[g][2], bf[g][3],
                       &Bb[(ks * 16 + brow) * LDB + bcol + g * 16]);
#pragma unroll
            for (int mt = 0; mt < 4; mt++)
#pragma unroll
                for (int nt = 0; nt < 4; nt++)
                    mma16(acc[mt][nt], af[mt], &bf[nt >> 1][(nt & 1) * 2]);
        }
        __syncthreads();
        if (s + 2 < NS) issue(s + 2);
        CPA_COMMIT();
    }

    // Epilogue
#pragma unroll
    for (int mt = 0; mt < 4; mt++) {
#pragma unroll
        for (int e2 = 0; e2 < 2; e2++) {
            int r = row0 + wm * 64 + mt * 16 + (lane >> 2) + e2 * 8;
#pragma unroll
            for (int nt = 0; nt < 4; nt++) {
                int c = col0 + wn * 32 + nt * 8 + (lane & 3) * 2;
                float v0 = acc[mt][nt][e2 * 2 + 0] + bias[c];
                float v1 = acc[mt][nt][e2 * 2 + 1] + bias[c + 1];
                if (QKV) {
                    int bb = r >> 11, t = r & 2047;
                    int sec = c >> 10, within = c & 1023;
                    int h = within >> 6, d = within & 63;
                    size_t idx = ((((size_t)bb * Hx + h) * Tx) + t) * HDx + d;
                    if (sec == 0) {
                        *(__half2*)&g_qh[idx] = __floats2half2_rn(v0 * 0.125f, v1 * 0.125f);
                    } else if (sec == 1) {
                        *(float2*)&kout[idx] = make_float2(v0, v1);
                        *(__half2*)&g_kh[idx] = __floats2half2_rn(v0, v1);
                    } else {
                        *(float2*)&vout[idx] = make_float2(v0, v1);
                        *(__half2*)&g_vh[idx] = __floats2half2_rn(v0, v1);
                    }
                } else {
                    *(float2*)&Y[(size_t)r * NN + c] = make_float2(v0, v1);
                }
            }
        }
    }
}

// ---------------------------------------------------------------------------
// Register-resident flash attention (FA2-style), causal.
// CTA = 128 q-rows x 64 kv-cols. 8 warps, each owns 16 full rows.
// S accum fragments -> half2 in regs -> PV A-fragments directly.
// Softmax reductions: 2x shfl_xor over 4 lanes. No S/P smem roundtrip.
// Grid (16 qtiles, 32 bh).
// ---------------------------------------------------------------------------
#define ALD 72
#define ATTN_SMEM ((128*ALD + 2*64*ALD + 2*64*ALD) * 2)   // Q + Kdb + Vdb = 55296 B

__global__ __launch_bounds__(256, 2) void attn_h_kernel()
{
    extern __shared__ char smc[];
    __half* Qh = (__half*)smc;                 // [128][ALD]
    __half* Kh = Qh + 128 * ALD;               // [2][64][ALD]
    __half* Vh = Kh + 2 * 64 * ALD;            // [2][64][ALD]

    int tid = threadIdx.x, lane = tid & 31, w = tid >> 5;
    int qt = blockIdx.x, bh = blockIdx.y;
    int g = lane >> 2, t4 = lane & 3;

    const __half* Qg = g_qh + ((size_t)bh * Tx + (size_t)qt * 128) * HDx;
    const __half* Kb0 = g_kh + (size_t)bh * Tx * HDx;
    const __half* Vb0 = g_vh + (size_t)bh * Tx * HDx;

    const int jend = 2 * qt + 2;

    auto issue_kv = [&](int j) {
        int buf = j & 1;
        const __half* Kg = Kb0 + (size_t)j * 64 * HDx;
        const __half* Vg = Vb0 + (size_t)j * 64 * HDx;
#pragma unroll
        for (int i = 0; i < 2; i++) {
            int c = i * 256 + tid;
            int r = c >> 3, o = (c & 7) * 8;
            cpa16(Kg + (size_t)r * HDx + o, &Kh[(buf * 64 + r) * ALD + o]);
            cpa16(Vg + (size_t)r * HDx + o, &Vh[(buf * 64 + r) * ALD + o]);
        }
    };

    // Q load (group 0) + KV0 (group 0) ; KV1 (group 1)
#pragma unroll
    for (int i = 0; i < 4; i++) {
        int c = i * 256 + tid;
        int r = c >> 3, o = (c & 7) * 8;
        cpa16(Qg + (size_t)r * HDx + o, &Qh[r * ALD + o]);
    }
    issue_kv(0); CPA_COMMIT();
    if (jend > 1) issue_kv(1);
    CPA_COMMIT();

    CPA_WAIT1();
    __syncthreads();

    // Resident Q fragments: warp rows [w*16, w*16+16)
    unsigned qf[4][4];
    {
        int arow = w * 16 + (lane & 15);
        int acol = (lane >> 4) * 8;
#pragma unroll
        for (int ks = 0; ks < 4; ks++)
            ldsm4(qf[ks][0], qf[ks][1], qf[ks][2], qf[ks][3],
                  &Qh[arow * ALD + ks * 16 + acol]);
    }

    float o[8][4];
#pragma unroll
    for (int nt = 0; nt < 8; nt++)
#pragma unroll
        for (int e = 0; e < 4; e++) o[nt][e] = 0.f;
    float m0 = -1e30f, m1 = -1e30f, l0 = 0.f, l1 = 0.f;

    int krow = (lane >> 4) * 8 + (lane & 7);
    int kcol = ((lane >> 3) & 1) * 8;
    int vrow = lane & 15;
    int vcol = (lane >> 4) * 8;

    int row0g = qt * 128 + w * 16 + g;      // global row (first half)

    for (int j = 0; j < jend; j++) {
        int buf = j & 1;
        const __half* Kb = &Kh[buf * 64 * ALD];
        const __half* Vb = &Vh[buf * 64 * ALD];

        // Warps 0-3 fully masked on the last tile: skip compute.
        bool active = !(j == 2 * qt + 1 && w < 4);

        if (active) {
            // ---- S = Q K^T : warp 16 rows x 64 toks = 8 n-tiles ----
            float s[8][4];
#pragma unroll
            for (int nt = 0; nt < 8; nt++)
#pragma unroll
                for (int e = 0; e < 4; e++) s[nt][e] = 0.f;

#pragma unroll
            for (int ks = 0; ks < 4; ks++) {
                unsigned bf[4][4];
#pragma unroll
                for (int gg = 0; gg < 4; gg++)
                    ldsm4(bf[gg][0], bf[gg][1], bf[gg][2], bf[gg][3],
                          &Kb[(gg * 16 + krow) * ALD + ks * 16 + kcol]);
#pragma unroll
                for (int nt = 0; nt < 8; nt++)
                    mma16(s[nt], qf[ks], &bf[nt >> 1][(nt & 1) * 2]);
            }

            // ---- causal mask (only last two tiles can touch diagonal) ----
            if (j >= 2 * qt) {
                int colbase = j * 64 + t4 * 2;
#pragma unroll
                for (int nt = 0; nt < 8; nt++) {
                    int c0 = colbase + nt * 8;
                    if (c0 > row0g)          s[nt][0] = -1e30f;
                    if (c0 + 1 > row0g)      s[nt][1] = -1e30f;
                    if (c0 > row0g + 8)      s[nt][2] = -1e30f;
                    if (c0 + 1 > row0g + 8)  s[nt][3] = -1e30f;
                }
            }

            // ---- online softmax, all in registers ----
            float mx0 = s[0][0], mx1 = s[0][2];
#pragma unroll
            for (int nt = 0; nt < 8; nt++) {
                mx0 = fmaxf(mx0, fmaxf(s[nt][0], s[nt][1]));
                mx1 = fmaxf(mx1, fmaxf(s[nt][2], s[nt][3]));
            }
            mx0 = fmaxf(mx0, __shfl_xor_sync(0xffffffffu, mx0, 1));
            mx0 = fmaxf(mx0, __shfl_xor_sync(0xffffffffu, mx0, 2));
            mx1 = fmaxf(mx1, __shfl_xor_sync(0xffffffffu, mx1, 1));
            mx1 = fmaxf(mx1, __shfl_xor_sync(0xffffffffu, mx1, 2));

            float mn0 = fmaxf(m0, mx0), mn1 = fmaxf(m1, mx1);
            float al0 = __expf(m0 - mn0), al1 = __expf(m1 - mn1);
            m0 = mn0; m1 = mn1;

            unsigned p0[8], p1[8];       // half2 P rows g / g+8
            float rs0 = 0.f, rs1 = 0.f;
#pragma unroll
            for (int nt = 0; nt < 8; nt++) {
                float e0 = __expf(s[nt][0] - mn0);
                float e1 = __expf(s[nt][1] - mn0);
                float e2 = __expf(s[nt][2] - mn1);
                float e3 = __expf(s[nt][3] - mn1);
                rs0 += e0 + e1; rs1 += e2 + e3;
                p0[nt] = h2u(__floats2half2_rn(e0, e1));
                p1[nt] = h2u(__floats2half2_rn(e2, e3));
            }
            rs0 += __shfl_xor_sync(0xffffffffu, rs0, 1);
            rs0 += __shfl_xor_sync(0xffffffffu, rs0, 2);
            rs1 += __shfl_xor_sync(0xffffffffu, rs1, 1);
            rs1 += __shfl_xor_sync(0xffffffffu, rs1, 2);
            l0 = l0 * al0 + rs0;
            l1 = l1 * al1 + rs1;

#pragma unroll
            for (int nt = 0; nt < 8; nt++) {
                o[nt][0] *= al0; o[nt][1] *= al0;
                o[nt][2] *= al1; o[nt][3] *= al1;
            }

            // ---- O += P V : A-fragments come straight from p0/p1 ----
#pragma unroll
            for (int ks = 0; ks < 4; ks++) {
                unsigned bf[4][4];
#pragma unroll
                for (int gg = 0; gg < 4; gg++)
                    ldsm4t(bf[gg][0], bf[gg][1], bf[gg][2], bf[gg][3],
                           &Vb[(ks * 16 + vrow) * ALD + gg * 16 + vcol]);
                unsigned aP[4] = {p0[2 * ks], p1[2 * ks], p0[2 * ks + 1], p1[2 * ks + 1]};
#pragma unroll
                for (int nt = 0; nt < 8; nt++)
                    mma16(o[nt], aP, &bf[nt >> 1][(nt & 1) * 2]);
            }
        }

        __syncthreads();                 // all warps done with buf
        if (j + 2 < jend) issue_kv(j + 2);
        CPA_COMMIT();
        if (j + 1 < jend) { CPA_WAIT1(); __syncthreads(); }
    }

    // ---- normalize + write atto (fp16) ----
    int bb = bh >> 4, h = bh & 15;
    float inv0 = 1.0f / l0, inv1 = 1.0f / l1;
    int r0 = qt * 128 + w * 16 + g;
#pragma unroll
    for (int nt = 0; nt < 8; nt++) {
        int c = nt * 8 + t4 * 2;
        *(__half2*)&g_attoh[((size_t)bb * Tx + r0) * Cx + h * 64 + c] =
            __floats2half2_rn(o[nt][0] * inv0, o[nt][1] * inv0);
        *(__half2*)&g_attoh[((size_t)bb * Tx + r0 + 8) * Cx + h * 64 + c] =
            __floats2half2_rn(o[nt][2] * inv1, o[nt][3] * inv1);
    }
}

// ---------------------------------------------------------------------------
extern "C" void kernel_launch(void* const* d_in, const int* in_sizes, int n_in,
                              void* d_out, int out_size)
{
    const float* x      = (const float*)d_in[0];
    const float* W_attn = (const float*)d_in[1];
    const float* b_attn = (const float*)d_in[2];
    const float* W_proj = (const float*)d_in[3];
    const float* b_proj = (const float*)d_in[4];

    float* y    = (float*)d_out;
    float* kout = y + (size_t)Bx * Tx * Cx;
    float* vout = kout + (size_t)Bx * Hx * Tx * HDx;

    cudaFuncSetAttribute(gemm_h_kernel<N_QKV, true>,
                         cudaFuncAttributeMaxDynamicSharedMemorySize, GEMM_SMEM);
    cudaFuncSetAttribute(gemm_h_kernel<Cx, false>,
                         cudaFuncAttributeMaxDynamicSharedMemorySize, GEMM_SMEM);
    cudaFuncSetAttribute(attn_h_kernel,
                         cudaFuncAttributeMaxDynamicSharedMemorySize, ATTN_SMEM);

    const int TOT4 = (Mx * Cx + Cx * N_QKV + Cx * Cx) / 4;
    convert_inputs_kernel<<<TOT4 / 256, 256>>>(x, W_attn, W_proj);
    gemm_h_kernel<N_QKV, true><<<dim3(N_QKV / 128, Mx / 128), 256, GEMM_SMEM>>>(
        b_attn, nullptr, kout, vout);
    attn_h_kernel<<<dim3(Tx / 128, Bx * Hx), 256, ATTN_SMEM>>>();
    gemm_h_kernel<Cx, false><<<dim3(Cx / 128, Mx / 128), 256, GEMM_SMEM>>>(
        b_proj, y, nullptr, nullptr);
}

// round 11
// speedup vs baseline: 6.2245x; 1.5313x over previous
#include <cuda_runtime.h>
#include <cuda_fp16.h>
#include <cstdint>

// Problem constants
#define Bx 2
#define Tx 2048
#define Cx 1024
#define Hx 16
#define HDx 64
#define Mx (Bx*Tx)          // 4096
#define N_QKV (3*Cx)        // 3072

// fp16 scratch (device globals: allocation-free per harness rules)
__device__ __half g_xh[(size_t)Mx*Cx];
__device__ __half g_wah[(size_t)Cx*N_QKV];
__device__ __half g_wph[(size_t)Cx*Cx];
__device__ __half g_qh[(size_t)Bx*Hx*Tx*HDx];    // pre-scaled by 0.125
__device__ __half g_kh[(size_t)Bx*Hx*Tx*HDx];
__device__ __half g_vh[(size_t)Bx*Hx*Tx*HDx];
__device__ __half g_attoh[(size_t)Bx*Tx*Cx];

// ---------------------------------------------------------------------------
// helpers
// ---------------------------------------------------------------------------
__device__ __forceinline__ void mma16(float* c, const unsigned* a, const unsigned* b) {
    asm volatile(
        "mma.sync.aligned.m16n8k16.row.col.f32.f16.f16.f32 "
        "{%0,%1,%2,%3},{%4,%5,%6,%7},{%8,%9},{%0,%1,%2,%3};\n"
        : "+f"(c[0]), "+f"(c[1]), "+f"(c[2]), "+f"(c[3])
        : "r"(a[0]), "r"(a[1]), "r"(a[2]), "r"(a[3]), "r"(b[0]), "r"(b[1]));
}

__device__ __forceinline__ void ldsm4(unsigned& r0, unsigned& r1, unsigned& r2,
                                      unsigned& r3, const __half* p) {
    unsigned a = (unsigned)__cvta_generic_to_shared(p);
    asm volatile("ldmatrix.sync.aligned.m8n8.x4.shared.b16 {%0,%1,%2,%3},[%4];\n"
                 : "=r"(r0), "=r"(r1), "=r"(r2), "=r"(r3) : "r"(a));
}

__device__ __forceinline__ void ldsm4t(unsigned& r0, unsigned& r1, unsigned& r2,
                                       unsigned& r3, const __half* p) {
    unsigned a = (unsigned)__cvta_generic_to_shared(p);
    asm volatile("ldmatrix.sync.aligned.m8n8.x4.trans.shared.b16 {%0,%1,%2,%3},[%4];\n"
                 : "=r"(r0), "=r"(r1), "=r"(r2), "=r"(r3) : "r"(a));
}

__device__ __forceinline__ void cpa16(const __half* gptr, __half* sptr) {
    unsigned d = (unsigned)__cvta_generic_to_shared(sptr);
    asm volatile("cp.async.cg.shared.global [%0], [%1], 16;\n" :: "r"(d), "l"(gptr));
}
#define CPA_COMMIT() asm volatile("cp.async.commit_group;\n")
#define CPA_WAIT1()  asm volatile("cp.async.wait_group 1;\n" ::: "memory")
#define CPA_WAIT2()  asm volatile("cp.async.wait_group 2;\n" ::: "memory")

__device__ __forceinline__ unsigned h2u(__half2 h) {
    return *(unsigned*)&h;
}

// ---------------------------------------------------------------------------
// fp32 -> fp16 conversion pre-pass (x, W_attn, W_proj)
// ---------------------------------------------------------------------------
__global__ __launch_bounds__(256) void convert_inputs_kernel(
    const float* __restrict__ x, const float* __restrict__ wa,
    const float* __restrict__ wp)
{
    const int X4 = Mx * Cx / 4, WA4 = Cx * N_QKV / 4, WP4 = Cx * Cx / 4;
    int i = blockIdx.x * blockDim.x + threadIdx.x;
    const float* src; __half* dst; int off;
    if (i < X4)                 { src = x;  dst = g_xh;  off = i; }
    else if (i < X4 + WA4)      { src = wa; dst = g_wah; off = i - X4; }
    else if (i < X4 + WA4 + WP4){ src = wp; dst = g_wph; off = i - X4 - WA4; }
    else return;
    float4 v = *(const float4*)&src[(size_t)off * 4];
    *(__half2*)&dst[(size_t)off * 4]     = __floats2half2_rn(v.x, v.y);
    *(__half2*)&dst[(size_t)off * 4 + 2] = __floats2half2_rn(v.z, v.w);
}

// ---------------------------------------------------------------------------
// fp16 tensor-core GEMM, 4-stage cp.async ring, 1 barrier per k-chunk.
// Block 128x128, k-chunk 32, 8 warps (2m x 4n), warp tile 64x32, m16n8k16.
// ---------------------------------------------------------------------------
#define KCH 32
#define LDA 40      // 32 + 8 pad (halves)
#define LDB 136     // 128 + 8 pad (halves)
#define ASTG (128*LDA)   // 5120 halves
#define BSTG (KCH*LDB)   // 4352 halves
#define STAGES 4
#define GEMM_SMEM (STAGES*(ASTG+BSTG)*2)   // 75776 B

template <int NN, bool QKV>
__global__ __launch_bounds__(256, 2) void gemm_h_kernel(
    const float* __restrict__ bias, float* __restrict__ Y,
    float* __restrict__ kout, float* __restrict__ vout)
{
    const int K = Cx;
    const __half* A = QKV ? g_xh : g_attoh;
    const __half* W = QKV ? g_wah : g_wph;

    extern __shared__ __half sh[];
    __half* As = sh;                       // [STAGES][128][LDA]
    __half* Bs = sh + STAGES * ASTG;       // [STAGES][KCH][LDB]

    int tid = threadIdx.x, lane = tid & 31, w = tid >> 5;
    int wm = w >> 2, wn = w & 3;
    int row0 = blockIdx.y * 128, col0 = blockIdx.x * 128;

    auto issue = [&](int s) {
        int slot = s & 3;
        const __half* gA = A + (size_t)row0 * K + s * KCH;
#pragma unroll
        for (int i = 0; i < 2; i++) {
            int c = i * 256 + tid;              // 0..511
            int r = c >> 2, o = (c & 3) * 8;
            cpa16(gA + (size_t)r * K + o, &As[slot * ASTG + r * LDA + o]);
        }
        const __half* gB = W + (size_t)(s * KCH) * NN + col0;
#pragma unroll
        for (int i = 0; i < 2; i++) {
            int c = i * 256 + tid;
            int r = c >> 4, o = (c & 15) * 8;
            cpa16(gB + (size_t)r * NN + o, &Bs[slot * BSTG + r * LDB + o]);
        }
    };

    float acc[4][4][4];
#pragma unroll
    for (int mt = 0; mt < 4; mt++)
#pragma unroll
        for (int nt = 0; nt < 4; nt++)
#pragma unroll
            for (int e = 0; e < 4; e++) acc[mt][nt][e] = 0.f;

    issue(0); CPA_COMMIT();
    issue(1); CPA_COMMIT();
    issue(2); CPA_COMMIT();

    int arow = wm * 64 + (lane & 15);
    int acol = (lane >> 4) * 8;
    int brow = lane & 15;
    int bcol = wn * 32 + (lane >> 4) * 8;

    const int NS = K / KCH;   // 32
    for (int s = 0; s < NS; s++) {
        CPA_WAIT2();
        __syncthreads();                   // stage s ready; slot (s-1)&3 free
        if (s + 3 < NS) issue(s + 3);      // into slot (s+3)&3 == (s-1)&3
        CPA_COMMIT();                      // unconditional: keeps group count exact

        int slot = s & 3;
        const __half* Ab = &As[slot * ASTG];
        const __half* Bb = &Bs[slot * BSTG];
#pragma unroll
        for (int ks = 0; ks < 2; ks++) {
            unsigned af[4][4], bf[2][4];
#pragma unroll
            for (int mt = 0; mt < 4; mt++)
                ldsm4(af[mt][0], af[mt][1], af[mt][2], af[mt][3],
                      &Ab[(arow + mt * 16) * LDA + ks * 16 + acol]);
#pragma unroll
            for (int g = 0; g < 2; g++)
                ldsm4t(bf[g][0], bf[g][1], bf[g][2], bf[g][3],
                       &Bb[(ks * 16 + brow) * LDB + bcol + g * 16]);
#pragma unroll
            for (int mt = 0; mt < 4; mt++)
#pragma unroll
                for (int nt = 0; nt < 4; nt++)
                    mma16(acc[mt][nt], af[mt], &bf[nt >> 1][(nt & 1) * 2]);
        }
    }

    // Epilogue
#pragma unroll
    for (int mt = 0; mt < 4; mt++) {
#pragma unroll
        for (int e2 = 0; e2 < 2; e2++) {
            int r = row0 + wm * 64 + mt * 16 + (lane >> 2) + e2 * 8;
#pragma unroll
            for (int nt = 0; nt < 4; nt++) {
                int c = col0 + wn * 32 + nt * 8 + (lane & 3) * 2;
                float v0 = acc[mt][nt][e2 * 2 + 0] + bias[c];
                float v1 = acc[mt][nt][e2 * 2 + 1] + bias[c + 1];
                if (QKV) {
                    int bb = r >> 11, t = r & 2047;
                    int sec = c >> 10, within = c & 1023;
                    int h = within >> 6, d = within & 63;
                    size_t idx = ((((size_t)bb * Hx + h) * Tx) + t) * HDx + d;
                    if (sec == 0) {
                        *(__half2*)&g_qh[idx] = __floats2half2_rn(v0 * 0.125f, v1 * 0.125f);
                    } else if (sec == 1) {
                        *(float2*)&kout[idx] = make_float2(v0, v1);
                        *(__half2*)&g_kh[idx] = __floats2half2_rn(v0, v1);
                    } else {
                        *(float2*)&vout[idx] = make_float2(v0, v1);
                        *(__half2*)&g_vh[idx] = __floats2half2_rn(v0, v1);
                    }
                } else {
                    *(float2*)&Y[(size_t)r * NN + c] = make_float2(v0, v1);
                }
            }
        }
    }
}

// ---------------------------------------------------------------------------
// Register-resident flash attention (FA2), causal. 3-stage KV ring,
// one barrier per tile. CTA = 128 q-rows x 64 kv-cols, 8 warps x 16 rows.
// Grid (16 qtiles, 32 bh).
// ---------------------------------------------------------------------------
#define ALD 72
#define KVSTG (64*ALD)
#define ATTN_SMEM ((128*ALD + 3*KVSTG + 3*KVSTG) * 2)   // 73728 B

__global__ __launch_bounds__(256, 2) void attn_h_kernel()
{
    extern __shared__ char smc[];
    __half* Qh = (__half*)smc;                 // [128][ALD]
    __half* Kh = Qh + 128 * ALD;               // [3][64][ALD]
    __half* Vh = Kh + 3 * KVSTG;               // [3][64][ALD]

    int tid = threadIdx.x, lane = tid & 31, w = tid >> 5;
    int qt = blockIdx.x, bh = blockIdx.y;
    int g = lane >> 2, t4 = lane & 3;

    const __half* Qg = g_qh + ((size_t)bh * Tx + (size_t)qt * 128) * HDx;
    const __half* Kb0 = g_kh + (size_t)bh * Tx * HDx;
    const __half* Vb0 = g_vh + (size_t)bh * Tx * HDx;

    const int jend = 2 * qt + 2;

    auto issue_kv = [&](int j) {
        int slot = j % 3;
        const __half* Kg = Kb0 + (size_t)j * 64 * HDx;
        const __half* Vg = Vb0 + (size_t)j * 64 * HDx;
#pragma unroll
        for (int i = 0; i < 2; i++) {
            int c = i * 256 + tid;
            int r = c >> 3, o = (c & 7) * 8;
            cpa16(Kg + (size_t)r * HDx + o, &Kh[slot * KVSTG + r * ALD + o]);
            cpa16(Vg + (size_t)r * HDx + o, &Vh[slot * KVSTG + r * ALD + o]);
        }
    };

    // group 0: Q + KV0 ; group 1: KV1
#pragma unroll
    for (int i = 0; i < 4; i++) {
        int c = i * 256 + tid;
        int r = c >> 3, o = (c & 7) * 8;
        cpa16(Qg + (size_t)r * HDx + o, &Qh[r * ALD + o]);
    }
    issue_kv(0); CPA_COMMIT();
    if (jend > 1) issue_kv(1);
    CPA_COMMIT();

    CPA_WAIT1();
    __syncthreads();                    // Q + KV0 ready

    // Resident Q fragments: warp rows [w*16, w*16+16)
    unsigned qf[4][4];
    {
        int arow = w * 16 + (lane & 15);
        int acol = (lane >> 4) * 8;
#pragma unroll
        for (int ks = 0; ks < 4; ks++)
            ldsm4(qf[ks][0], qf[ks][1], qf[ks][2], qf[ks][3],
                  &Qh[arow * ALD + ks * 16 + acol]);
    }

    float o[8][4];
#pragma unroll
    for (int nt = 0; nt < 8; nt++)
#pragma unroll
        for (int e = 0; e < 4; e++) o[nt][e] = 0.f;
    float m0 = -1e30f, m1 = -1e30f, l0 = 0.f, l1 = 0.f;

    int krow = (lane >> 4) * 8 + (lane & 7);
    int kcol = ((lane >> 3) & 1) * 8;
    int vrow = lane & 15;
    int vcol = (lane >> 4) * 8;

    int row0g = qt * 128 + w * 16 + g;

    for (int j = 0; j < jend; j++) {
        if (j > 0) { CPA_WAIT1(); __syncthreads(); }  // KV_j ready; slot (j-1)%3 free
        if (j + 2 < jend) issue_kv(j + 2);            // into slot (j+2)%3 == (j-1)%3
        CPA_COMMIT();

        int slot = j % 3;
        const __half* Kb = &Kh[slot * KVSTG];
        const __half* Vb = &Vh[slot * KVSTG];

        bool active = !(j == 2 * qt + 1 && w < 4);

        if (active) {
            // ---- S = Q K^T ----
            float s[8][4];
#pragma unroll
            for (int nt = 0; nt < 8; nt++)
#pragma unroll
                for (int e = 0; e < 4; e++) s[nt][e] = 0.f;

#pragma unroll
            for (int ks = 0; ks < 4; ks++) {
                unsigned bf[4][4];
#pragma unroll
                for (int gg = 0; gg < 4; gg++)
                    ldsm4(bf[gg][0], bf[gg][1], bf[gg][2], bf[gg][3],
                          &Kb[(gg * 16 + krow) * ALD + ks * 16 + kcol]);
#pragma unroll
                for (int nt = 0; nt < 8; nt++)
                    mma16(s[nt], qf[ks], &bf[nt >> 1][(nt & 1) * 2]);
            }

            // ---- causal mask ----
            if (j >= 2 * qt) {
                int colbase = j * 64 + t4 * 2;
#pragma unroll
                for (int nt = 0; nt < 8; nt++) {
                    int c0 = colbase + nt * 8;
                    if (c0 > row0g)          s[nt][0] = -1e30f;
                    if (c0 + 1 > row0g)      s[nt][1] = -1e30f;
                    if (c0 > row0g + 8)      s[nt][2] = -1e30f;
                    if (c0 + 1 > row0g + 8)  s[nt][3] = -1e30f;
                }
            }

            // ---- online softmax (registers + 4-lane shfl) ----
            float mx0 = s[0][0], mx1 = s[0][2];
#pragma unroll
            for (int nt = 0; nt < 8; nt++) {
                mx0 = fmaxf(mx0, fmaxf(s[nt][0], s[nt][1]));
                mx1 = fmaxf(mx1, fmaxf(s[nt][2], s[nt][3]));
            }
            mx0 = fmaxf(mx0, __shfl_xor_sync(0xffffffffu, mx0, 1));
            mx0 = fmaxf(mx0, __shfl_xor_sync(0xffffffffu, mx0, 2));
            mx1 = fmaxf(mx1, __shfl_xor_sync(0xffffffffu, mx1, 1));
            mx1 = fmaxf(mx1, __shfl_xor_sync(0xffffffffu, mx1, 2));

            float mn0 = fmaxf(m0, mx0), mn1 = fmaxf(m1, mx1);
            float al0 = __expf(m0 - mn0), al1 = __expf(m1 - mn1);
            m0 = mn0; m1 = mn1;

            unsigned p0[8], p1[8];
            float rs0 = 0.f, rs1 = 0.f;
#pragma unroll
            for (int nt = 0; nt < 8; nt++) {
                float e0 = __expf(s[nt][0] - mn0);
                float e1 = __expf(s[nt][1] - mn0);
                float e2 = __expf(s[nt][2] - mn1);
                float e3 = __expf(s[nt][3] - mn1);
                rs0 += e0 + e1; rs1 += e2 + e3;
                p0[nt] = h2u(__floats2half2_rn(e0, e1));
                p1[nt] = h2u(__floats2half2_rn(e2, e3));
            }
            rs0 += __shfl_xor_sync(0xffffffffu, rs0, 1);
            rs0 += __shfl_xor_sync(0xffffffffu, rs0, 2);
            rs1 += __shfl_xor_sync(0xffffffffu, rs1, 1);
            rs1 += __shfl_xor_sync(0xffffffffu, rs1, 2);
            l0 = l0 * al0 + rs0;
            l1 = l1 * al1 + rs1;

#pragma unroll
            for (int nt = 0; nt < 8; nt++) {
                o[nt][0] *= al0; o[nt][1] *= al0;
                o[nt][2] *= al1; o[nt][3] *= al1;
            }

            // ---- O += P V ----
#pragma unroll
            for (int ks = 0; ks < 4; ks++) {
                unsigned bf[4][4];
#pragma unroll
                for (int gg = 0; gg < 4; gg++)
                    ldsm4t(bf[gg][0], bf[gg][1], bf[gg][2], bf[gg][3],
                           &Vb[(ks * 16 + vrow) * ALD + gg * 16 + vcol]);
                unsigned aP[4] = {p0[2 * ks], p1[2 * ks], p0[2 * ks + 1], p1[2 * ks + 1]};
#pragma unroll
                for (int nt = 0; nt < 8; nt++)
                    mma16(o[nt], aP, &bf[nt >> 1][(nt & 1) * 2]);
            }
        }
    }

    // ---- normalize + write atto (fp16) ----
    int bb = bh >> 4, h = bh & 15;
    float inv0 = 1.0f / l0, inv1 = 1.0f / l1;
    int r0 = qt * 128 + w * 16 + g;
#pragma unroll
    for (int nt = 0; nt < 8; nt++) {
        int c = nt * 8 + t4 * 2;
        *(__half2*)&g_attoh[((size_t)bb * Tx + r0) * Cx + h * 64 + c] =
            __floats2half2_rn(o[nt][0] * inv0, o[nt][1] * inv0);
        *(__half2*)&g_attoh[((size_t)bb * Tx + r0 + 8) * Cx + h * 64 + c] =
            __floats2half2_rn(o[nt][2] * inv1, o[nt][3] * inv1);
    }
}

// ---------------------------------------------------------------------------
extern "C" void kernel_launch(void* const* d_in, const int* in_sizes, int n_in,
                              void* d_out, int out_size)
{
    const float* x      = (const float*)d_in[0];
    const float* W_attn = (const float*)d_in[1];
    const float* b_attn = (const float*)d_in[2];
    const float* W_proj = (const float*)d_in[3];
    const float* b_proj = (const float*)d_in[4];

    float* y    = (float*)d_out;
    float* kout = y + (size_t)Bx * Tx * Cx;
    float* vout = kout + (size_t)Bx * Hx * Tx * HDx;

    cudaFuncSetAttribute(gemm_h_kernel<N_QKV, true>,
                         cudaFuncAttributeMaxDynamicSharedMemorySize, GEMM_SMEM);
    cudaFuncSetAttribute(gemm_h_kernel<Cx, false>,
                         cudaFuncAttributeMaxDynamicSharedMemorySize, GEMM_SMEM);
    cudaFuncSetAttribute(attn_h_kernel,
                         cudaFuncAttributeMaxDynamicSharedMemorySize, ATTN_SMEM);

    const int TOT4 = (Mx * Cx + Cx * N_QKV + Cx * Cx) / 4;
    convert_inputs_kernel<<<TOT4 / 256, 256>>>(x, W_attn, W_proj);
    gemm_h_kernel<N_QKV, true><<<dim3(N_QKV / 128, Mx / 128), 256, GEMM_SMEM>>>(
        b_attn, nullptr, kout, vout);
    attn_h_kernel<<<dim3(Tx / 128, Bx * Hx), 256, ATTN_SMEM>>>();
    gemm_h_kernel<Cx, false><<<dim3(Cx / 128, Mx / 128), 256, GEMM_SMEM>>>(
        b_proj, y, nullptr, nullptr);
}